// round 10
// baseline (speedup 1.0000x reference)
#include <cuda_runtime.h>
#include <math.h>

// ChamferLoss_31044023616212: one-sided Chamfer distance
//   set1: [2, 8192, 3] f32, set2: [2, 8192, 3] f32 -> scalar f32
//
// R9: brute force is at the FP32 FMA roofline (~37us: FFMA2 occupies the
// 16-lane fma pipe 4cyc/instr -> packed math is throughput-neutral).
// Switch to exact z-bucket pruning:
//   kernel 1: bucket set2 by z into 512 bins (histogram+prefix+scatter).
//   kernel 2: per x, scan buckets outward from x's bin; stop a direction
//             when (near-edge dz)^2 >= best d^2 (exact lower bound).
// Per x: ~300-600 candidates instead of 8192 (~20x less FMA work).
// m = |y|^2 - 2<x,y>; d = sqrt(max(min m + |x|^2, 0)) -- same identity
// as the reference. fminf over a bucket is order-invariant, so the
// atomic scatter order does not affect the output (deterministic).

#define NBATCH 2
#define NPTS   8192
#define NB     512                 // z-buckets
#define ZMIN   (-6.0f)
#define ZWID   (12.0f / NB)
#define ZINV   (NB / 12.0f)

#define SB     32                  // search blocks per batch
#define ST     256                 // search threads per block
#define NPART  (SB * NBATCH)       // 64 partials

__device__ float4 g_pts[NBATCH][NPTS];     // bucketed (y0,y1,y2,|y|^2)
__device__ int    g_boff[NBATCH][NB + 1];  // bucket start offsets
__device__ float  g_partials[NPART];
__device__ int    g_count = 0;

// ---------------- kernel 1: bucket set2 by z ----------------
extern "C" __global__ void __launch_bounds__(1024, 1)
bucket_kernel(const float* __restrict__ set2, int n)
{
    __shared__ int hist[NB];
    __shared__ int offs[NB + 1];
    __shared__ int cur[NB];

    const int b   = blockIdx.x;
    const int tid = threadIdx.x;
    const float* p2 = set2 + (size_t)b * n * 3;

    for (int i = tid; i < NB; i += 1024) hist[i] = 0;
    __syncthreads();

    for (int j = tid; j < n; j += 1024) {
        float z = p2[3 * j + 2];
        int ib = (int)((z - ZMIN) * ZINV);
        ib = min(max(ib, 0), NB - 1);
        atomicAdd(&hist[ib], 1);
    }
    __syncthreads();

    // exclusive prefix: offs[0]=0, offs[i+1]=sum hist[0..i]  (Hillis-Steele)
    if (tid < NB) offs[tid + 1] = hist[tid];
    if (tid == 0) offs[0] = 0;
    __syncthreads();
    for (int s = 1; s < NB; s <<= 1) {
        int add = 0;
        if (tid < NB && tid >= s) add = offs[tid + 1 - s];
        __syncthreads();
        if (tid < NB) offs[tid + 1] += add;
        __syncthreads();
    }

    if (tid < NB) cur[tid] = offs[tid];
    __syncthreads();

    for (int j = tid; j < n; j += 1024) {
        float y0 = p2[3 * j + 0];
        float y1 = p2[3 * j + 1];
        float y2 = p2[3 * j + 2];
        int ib = (int)((y2 - ZMIN) * ZINV);
        ib = min(max(ib, 0), NB - 1);
        int r = atomicAdd(&cur[ib], 1);
        g_pts[b][r] = make_float4(y0, y1, y2, y0 * y0 + y1 * y1 + y2 * y2);
    }

    if (tid < NB) g_boff[b][tid] = offs[tid];
    if (tid == 0) g_boff[b][NB] = offs[NB];
}

// ---------------- kernel 2: pruned nearest-neighbor search ----------------
extern "C" __global__ void __launch_bounds__(ST, 1)
search_kernel(const float* __restrict__ set1,
              float* __restrict__ out,
              int n)
{
    extern __shared__ float4 sp[];          // NPTS float4 candidates
    int* soff = (int*)(sp + NPTS);          // NB+1 offsets

    const int tid = threadIdx.x;
    const int bx  = blockIdx.x;
    const int b   = blockIdx.y;

    // cooperative stage of this batch's bucketed points + offsets
    const float4* gp = g_pts[b];
    for (int i = tid; i < n; i += ST) sp[i] = gp[i];
    for (int i = tid; i <= NB; i += ST) soff[i] = g_boff[b][i];
    __syncthreads();

    const int p = bx * ST + tid;            // this thread's set1 point
    const float* x = set1 + ((size_t)b * n + p) * 3;
    const float x0 = x[0], x1 = x[1], x2 = x[2];
    const float sqx = x0 * x0 + x1 * x1 + x2 * x2;

    int xb = (int)((x2 - ZMIN) * ZINV);
    xb = min(max(xb, 0), NB - 1);

    float best_m = 3.4e38f;                 // min over m = |y|^2 - 2<x,y>

    // scan own bucket first (good initial bound)
    {
        const int e = soff[xb + 1];
        for (int r = soff[xb]; r < e; ++r) {
            float4 q = sp[r];
            float dot = fmaf(x0, q.x, fmaf(x1, q.y, x2 * q.z));
            best_m = fminf(best_m, fmaf(-2.0f, dot, q.w));
        }
    }

    // expand outward; stop each direction when the bucket near-edge z-gap
    // already exceeds the best distance (exact lower bound, z-monotone).
    int up = xb + 1, dn = xb - 1;
    bool cu = (up < NB), cd = (dn >= 0);
    while (cu || cd) {
        if (cu) {
            float edge = ZMIN + up * ZWID;          // lowest z in bucket 'up'
            float dz = edge - x2;                    // > 0
            if (dz * dz >= best_m + sqx) {
                cu = false;
            } else {
                const int e = soff[up + 1];
                for (int r = soff[up]; r < e; ++r) {
                    float4 q = sp[r];
                    float dot = fmaf(x0, q.x, fmaf(x1, q.y, x2 * q.z));
                    best_m = fminf(best_m, fmaf(-2.0f, dot, q.w));
                }
                if (++up >= NB) cu = false;
            }
        }
        if (cd) {
            float edge = ZMIN + (dn + 1) * ZWID;    // highest z in bucket 'dn'
            float dz = x2 - edge;                    // > 0
            if (dz * dz >= best_m + sqx) {
                cd = false;
            } else {
                const int e = soff[dn + 1];
                for (int r = soff[dn]; r < e; ++r) {
                    float4 q = sp[r];
                    float dot = fmaf(x0, q.x, fmaf(x1, q.y, x2 * q.z));
                    best_m = fminf(best_m, fmaf(-2.0f, dot, q.w));
                }
                if (--dn < 0) cd = false;
            }
        }
    }

    float dist = sqrtf(fmaxf(best_m + sqx, 0.0f));

    // ---- deterministic block reduction ----
    #pragma unroll
    for (int o = 16; o > 0; o >>= 1)
        dist += __shfl_xor_sync(0xffffffffu, dist, o);

    __shared__ float wsum[ST / 32];
    if ((tid & 31) == 0) wsum[tid >> 5] = dist;
    __syncthreads();

    if (tid == 0) {
        float s = 0.0f;
        #pragma unroll
        for (int w = 0; w < ST / 32; ++w) s += wsum[w];
        g_partials[b * SB + bx] = s;
        __threadfence();
        int t = atomicAdd(&g_count, 1);
        if (t == NPART - 1) {
            float tot = 0.0f;
            #pragma unroll 4
            for (int i = 0; i < NPART; ++i) tot += g_partials[i];
            out[0]  = tot;
            g_count = 0;     // self-reset for graph replay
        }
    }
}

extern "C" void kernel_launch(void* const* d_in, const int* in_sizes, int n_in,
                              void* d_out, int out_size)
{
    const float* set1 = (const float*)d_in[0];
    const float* set2 = (const float*)d_in[1];

    // in_sizes[0] = b * n * d = 2 * n * 3
    const int n = in_sizes[0] / (NBATCH * 3);

    const size_t smem = (size_t)NPTS * sizeof(float4)    // candidates
                      + (NB + 1) * sizeof(int);          // offsets
    cudaFuncSetAttribute(search_kernel,
                         cudaFuncAttributeMaxDynamicSharedMemorySize, (int)smem);

    bucket_kernel<<<NBATCH, 1024>>>(set2, n);
    dim3 grid(SB, NBATCH);
    search_kernel<<<grid, ST, smem>>>(set1, (float*)d_out, n);
}